// round 4
// baseline (speedup 1.0000x reference)
#include <cuda_runtime.h>
#include <cstdint>

#define N_NODES 40000
#define N_EDGES 640000
#define DF      128
#define N_GRAPHS 128

// -------- scratch (static device globals; no runtime allocation) ----------
__device__ float g_agg[(size_t)N_NODES * DF];
__device__ float g_h0 [(size_t)N_NODES * DF];
__device__ float g_h1 [(size_t)N_NODES * DF];
__device__ int   g_rowptr[N_NODES + 1];
__device__ int   g_deg [N_NODES];
__device__ int   g_fill[N_NODES];
__device__ int   g_colidx[N_EDGES];
__device__ unsigned g_outmax[N_GRAPHS * DF];
__device__ int   g_is64;

// -------- float <-> monotone unsigned for atomicMax ----------
__device__ __forceinline__ unsigned enc_f(float f) {
    unsigned b = __float_as_uint(f);
    return (b & 0x80000000u) ? ~b : (b | 0x80000000u);
}
__device__ __forceinline__ float dec_f(unsigned u) {
    unsigned b = (u & 0x80000000u) ? (u ^ 0x80000000u) : ~u;
    return __uint_as_float(b);
}
// enc(bits(-inf)) = ~0xFF800000 = 0x007FFFFF
#define ENC_NEG_INF 0x007FFFFFu

// -------- probe: int64 vs int32 edge indices ----------
// Edge values < 40000 (17 bits). If int64, every odd 32-bit word is 0.
// If int32, odd words are random node ids (P[256 all zero] ~ 0).
__global__ void k_probe(const int* __restrict__ ew) {
    int any_nonzero = 0;
    for (int i = 0; i < 256; i++) {
        if (ew[2 * i + 1] != 0) { any_nonzero = 1; break; }
    }
    g_is64 = any_nonzero ? 0 : 1;
}

// -------- zero/init ----------
__global__ void k_zero() {
    int i = blockIdx.x * blockDim.x + threadIdx.x;
    if (i < N_NODES) { g_deg[i] = 0; g_fill[i] = 0; }
    if (i < N_GRAPHS * DF) g_outmax[i] = ENC_NEG_INF;
}

// -------- CSR build ----------
__global__ void k_count(const int* __restrict__ ew) {
    int e = blockIdx.x * blockDim.x + threadIdx.x;
    if (e >= N_EDGES) return;
    int dst = g_is64 ? ew[2 * (N_EDGES + e)] : ew[N_EDGES + e];
    atomicAdd(&g_deg[dst], 1);
}

__global__ void k_scan() {
    const int CH = 40;  // 1024*40 >= 40000
    __shared__ int part[1024];
    int t = threadIdx.x;
    int beg = t * CH;
    int end = beg + CH; if (end > N_NODES) end = N_NODES;
    int s = 0;
    for (int i = beg; i < end; i++) s += g_deg[i];
    part[t] = s;
    __syncthreads();
    for (int off = 1; off < 1024; off <<= 1) {
        int v = (t >= off) ? part[t - off] : 0;
        __syncthreads();
        part[t] += v;
        __syncthreads();
    }
    int run = (t == 0) ? 0 : part[t - 1];
    for (int i = beg; i < end; i++) {
        g_rowptr[i] = run;
        run += g_deg[i];
    }
    if (t == 1023) g_rowptr[N_NODES] = part[1023];
}

__global__ void k_fill(const int* __restrict__ ew) {
    int e = blockIdx.x * blockDim.x + threadIdx.x;
    if (e >= N_EDGES) return;
    int is64 = g_is64;
    int src = is64 ? ew[2 * e] : ew[e];
    int dst = is64 ? ew[2 * (N_EDGES + e)] : ew[N_EDGES + e];
    int pos = atomicAdd(&g_fill[dst], 1);
    g_colidx[g_rowptr[dst] + pos] = src;
}

// -------- edge aggregation: one warp per node, register accumulate ----------
// 4-edge unroll, loads batched before adds (MLP ~ 8 per lane incl. float4 split).
// in_sel: 0 = external x, 1 = g_h0, 2 = g_h1.  Output always g_agg.
__global__ void __launch_bounds__(256) k_agg(const float* __restrict__ xext, int in_sel) {
    const float* xin = (in_sel == 0) ? xext : (in_sel == 1 ? g_h0 : g_h1);
    int gwarp = (blockIdx.x * blockDim.x + threadIdx.x) >> 5;
    int lane = threadIdx.x & 31;
    if (gwarp >= N_NODES) return;
    int beg = g_rowptr[gwarp];
    int end = g_rowptr[gwarp + 1];
    float4 acc = make_float4(0.f, 0.f, 0.f, 0.f);
    int e = beg;
    for (; e + 3 < end; e += 4) {
        int s0 = g_colidx[e + 0];
        int s1 = g_colidx[e + 1];
        int s2 = g_colidx[e + 2];
        int s3 = g_colidx[e + 3];
        float4 v0 = __ldg((const float4*)(xin + (size_t)s0 * DF) + lane);
        float4 v1 = __ldg((const float4*)(xin + (size_t)s1 * DF) + lane);
        float4 v2 = __ldg((const float4*)(xin + (size_t)s2 * DF) + lane);
        float4 v3 = __ldg((const float4*)(xin + (size_t)s3 * DF) + lane);
        acc.x += (v0.x + v1.x) + (v2.x + v3.x);
        acc.y += (v0.y + v1.y) + (v2.y + v3.y);
        acc.z += (v0.z + v1.z) + (v2.z + v3.z);
        acc.w += (v0.w + v1.w) + (v2.w + v3.w);
    }
    for (; e < end; e++) {
        int s0 = g_colidx[e];
        float4 v0 = __ldg((const float4*)(xin + (size_t)s0 * DF) + lane);
        acc.x += v0.x; acc.y += v0.y; acc.z += v0.z; acc.w += v0.w;
    }
    *((float4*)(g_agg + (size_t)gwarp * DF) + lane) = acc;
}

// -------- fused GEMM: out = [g_agg | root] @ [Wrel;Wroot] + b, opt ReLU ----
// BM=64, BN=128, BK=16, 128 threads, 8x8 per thread. K = 256 (virtual concat).
// root_sel: 0 = external x, 1 = g_h0, 2 = g_h1.  out_sel: 0 = g_h0, 1 = g_h1.
__global__ void __launch_bounds__(128) k_gemm(
    const float* __restrict__ xext, int root_sel, int out_sel,
    const float* __restrict__ Wrel, const float* __restrict__ Wroot,
    const float* __restrict__ bias, int do_relu)
{
    const float* Aroot = (root_sel == 0) ? xext : (root_sel == 1 ? g_h0 : g_h1);
    float* out = (out_sel == 0) ? g_h0 : g_h1;

    __shared__ float As[16][68];   // [k][row], padded (stride 272B, 16B-aligned)
    __shared__ float Bs[16][128];  // [k][col]

    int tid = threadIdx.x;
    int row0 = blockIdx.x * 64;
    int tx = tid & 15;   // col group
    int ty = tid >> 4;   // row group

    int a_k4  = tid & 3;   // float4 index along K
    int a_row = tid >> 2;  // 0..31 (handles rows a_row, a_row+32)
    int b_j4  = tid & 31;  // float4 col
    int b_kr  = tid >> 5;  // 0..3

    float acc[8][8];
    #pragma unroll
    for (int i = 0; i < 8; i++)
        #pragma unroll
        for (int j = 0; j < 8; j++) acc[i][j] = 0.f;

    for (int t = 0; t < 256; t += 16) {
        #pragma unroll
        for (int rr = 0; rr < 2; rr++) {
            int r = a_row + rr * 32;
            int gk = t + a_k4 * 4;
            const float* src = (gk < 128)
                ? (g_agg + (size_t)(row0 + r) * DF + gk)
                : (Aroot + (size_t)(row0 + r) * DF + (gk - 128));
            float4 v = *(const float4*)src;
            As[a_k4 * 4 + 0][r] = v.x;
            As[a_k4 * 4 + 1][r] = v.y;
            As[a_k4 * 4 + 2][r] = v.z;
            As[a_k4 * 4 + 3][r] = v.w;
        }
        #pragma unroll
        for (int kk = 0; kk < 4; kk++) {
            int k = b_kr + kk * 4;
            int gk = t + k;
            const float* src = (gk < 128)
                ? (Wrel  + (size_t)gk * DF + b_j4 * 4)
                : (Wroot + (size_t)(gk - 128) * DF + b_j4 * 4);
            *(float4*)&Bs[k][b_j4 * 4] = *(const float4*)src;
        }
        __syncthreads();

        #pragma unroll
        for (int k = 0; k < 16; k++) {
            float a[8], bv[8];
            *(float4*)&a[0]  = *(const float4*)&As[k][ty * 8];
            *(float4*)&a[4]  = *(const float4*)&As[k][ty * 8 + 4];
            *(float4*)&bv[0] = *(const float4*)&Bs[k][tx * 8];
            *(float4*)&bv[4] = *(const float4*)&Bs[k][tx * 8 + 4];
            #pragma unroll
            for (int i = 0; i < 8; i++)
                #pragma unroll
                for (int j = 0; j < 8; j++)
                    acc[i][j] += a[i] * bv[j];
        }
        __syncthreads();
    }

    #pragma unroll
    for (int i = 0; i < 8; i++) {
        int row = row0 + ty * 8 + i;
        #pragma unroll
        for (int j = 0; j < 8; j += 4) {
            int col = tx * 8 + j;
            float4 r;
            r.x = acc[i][j + 0] + bias[col + 0];
            r.y = acc[i][j + 1] + bias[col + 1];
            r.z = acc[i][j + 2] + bias[col + 2];
            r.w = acc[i][j + 3] + bias[col + 3];
            if (do_relu) {
                r.x = fmaxf(r.x, 0.f); r.y = fmaxf(r.y, 0.f);
                r.z = fmaxf(r.z, 0.f); r.w = fmaxf(r.w, 0.f);
            }
            *(float4*)(out + (size_t)row * DF + col) = r;
        }
    }
}

// -------- global max pool: reads g_h0 (layer-2 output) ----------
__global__ void k_pool(const int* __restrict__ batch) {
    int idx = blockIdx.x * blockDim.x + threadIdx.x;
    if (idx >= N_NODES * 32) return;
    int node = idx >> 5;
    int c = (idx & 31) * 4;
    int g = g_is64 ? batch[2 * node] : batch[node];
    float4 v = *(const float4*)(g_h0 + (size_t)node * DF + c);
    unsigned* o = &g_outmax[g * DF + c];
    atomicMax(o + 0, enc_f(v.x));
    atomicMax(o + 1, enc_f(v.y));
    atomicMax(o + 2, enc_f(v.z));
    atomicMax(o + 3, enc_f(v.w));
}

__global__ void k_decode(float* __restrict__ out) {
    int i = blockIdx.x * blockDim.x + threadIdx.x;
    if (i < N_GRAPHS * DF) out[i] = dec_f(g_outmax[i]);
}

// ---------------------------------------------------------------------------
extern "C" void kernel_launch(void* const* d_in, const int* in_sizes, int n_in,
                              void* d_out, int out_size) {
    const float* x      = (const float*)d_in[0];
    const int*   edges  = (const int*)  d_in[1];   // int32 or int64 (probed)
    const int*   batch  = (const int*)  d_in[2];
    const float* Wrel0  = (const float*)d_in[3];
    const float* brel0  = (const float*)d_in[4];
    const float* Wroot0 = (const float*)d_in[5];
    const float* Wrel1  = (const float*)d_in[6];
    const float* brel1  = (const float*)d_in[7];
    const float* Wroot1 = (const float*)d_in[8];
    const float* Wrel2  = (const float*)d_in[9];
    const float* brel2  = (const float*)d_in[10];
    const float* Wroot2 = (const float*)d_in[11];
    float* out = (float*)d_out;

    k_probe<<<1, 1>>>(edges);
    k_zero<<<(N_NODES + 255) / 256, 256>>>();
    k_count<<<N_EDGES / 256, 256>>>(edges);
    k_scan<<<1, 1024>>>();
    k_fill<<<N_EDGES / 256, 256>>>(edges);

    const int AGG_BLOCKS = N_NODES / 8;       // 8 warps/block, 1 node/warp
    const int GEMM_BLOCKS = N_NODES / 64;     // 625

    // layer 0: agg(x) -> gemm([agg|x]) -> h0 (ReLU)
    k_agg<<<AGG_BLOCKS, 256>>>(x, 0);
    k_gemm<<<GEMM_BLOCKS, 128>>>(x, 0, 0, Wrel0, Wroot0, brel0, 1);
    // layer 1: agg(h0) -> gemm([agg|h0]) -> h1 (ReLU)
    k_agg<<<AGG_BLOCKS, 256>>>(x, 1);
    k_gemm<<<GEMM_BLOCKS, 128>>>(x, 1, 1, Wrel1, Wroot1, brel1, 1);
    // layer 2: agg(h1) -> gemm([agg|h1]) -> h0 (no ReLU)
    k_agg<<<AGG_BLOCKS, 256>>>(x, 2);
    k_gemm<<<GEMM_BLOCKS, 128>>>(x, 2, 0, Wrel2, Wroot2, brel2, 0);

    // pool + decode
    k_pool<<<(N_NODES * 32 + 255) / 256, 256>>>(batch);
    k_decode<<<(N_GRAPHS * DF + 255) / 256, 256>>>(out);
}

// round 7
// speedup vs baseline: 1.5947x; 1.5947x over previous
#include <cuda_runtime.h>
#include <cstdint>

#define N_NODES 40000
#define N_EDGES 640000
#define DF      128
#define N_GRAPHS 128

// ======================= scratch (static device globals) ====================
__device__ float g_agg[(size_t)N_NODES * DF];
__device__ float g_h0 [(size_t)N_NODES * DF];
__device__ float g_h1 [(size_t)N_NODES * DF];
__device__ float g_WT [3][DF][256];          // [layer][n][k_cat] transposed weights
__device__ int   g_rowptr[N_NODES + 1];
__device__ int   g_deg [N_NODES];
__device__ int   g_fill[N_NODES];
__device__ int   g_colidx[N_EDGES];
__device__ int   g_bsum[160];
__device__ int   g_boff[160];
__device__ unsigned g_outmax[N_GRAPHS * DF];
__device__ int   g_is64;

// ======================= helpers ===========================================
__device__ __forceinline__ uint32_t f2tf32(float f) {
    uint32_t r;
    asm("cvt.rna.tf32.f32 %0, %1;" : "=r"(r) : "f"(f));
    return r;
}

// mma.sync m16n8k8 tf32: D(4f) = A(4r) * B(2r) + D
#define MMA_TF32(d, a, b0, b1)                                                \
    asm volatile("mma.sync.aligned.m16n8k8.row.col.f32.tf32.tf32.f32 "        \
        "{%0,%1,%2,%3}, {%4,%5,%6,%7}, {%8,%9}, {%0,%1,%2,%3};"               \
        : "+f"((d)[0]), "+f"((d)[1]), "+f"((d)[2]), "+f"((d)[3])              \
        : "r"((a)[0]), "r"((a)[1]), "r"((a)[2]), "r"((a)[3]),                 \
          "r"(b0), "r"(b1))

__device__ __forceinline__ unsigned enc_f(float f) {
    unsigned b = __float_as_uint(f);
    return (b & 0x80000000u) ? ~b : (b | 0x80000000u);
}
__device__ __forceinline__ float dec_f(unsigned u) {
    unsigned b = (u & 0x80000000u) ? (u ^ 0x80000000u) : ~u;
    return __uint_as_float(b);
}
#define ENC_NEG_INF 0x007FFFFFu

// ======================= probe + init ======================================
__global__ void k_probe(const int* __restrict__ ew) {
    int any_nonzero = 0;
    for (int i = 0; i < 256; i++)
        if (ew[2 * i + 1] != 0) { any_nonzero = 1; break; }
    g_is64 = any_nonzero ? 0 : 1;
}

__global__ void k_zero() {
    int i = blockIdx.x * blockDim.x + threadIdx.x;
    if (i < N_NODES) { g_deg[i] = 0; g_fill[i] = 0; }
    if (i < N_GRAPHS * DF) g_outmax[i] = ENC_NEG_INF;
}

// ======================= weight transpose: WT[n][k_cat] ====================
__global__ void k_wprep(const float* __restrict__ Wrel, const float* __restrict__ Wroot, int layer) {
    int idx = blockIdx.x * blockDim.x + threadIdx.x;
    if (idx >= DF * 256) return;
    int n = idx >> 8;
    int k = idx & 255;
    float v = (k < DF) ? Wrel[k * DF + n] : Wroot[(k - DF) * DF + n];
    g_WT[layer][n][k] = v;
}

// ======================= CSR build =========================================
__global__ void k_count(const int* __restrict__ ew) {
    int e = blockIdx.x * blockDim.x + threadIdx.x;
    if (e >= N_EDGES) return;
    int dst = g_is64 ? ew[2 * (N_EDGES + e)] : ew[N_EDGES + e];
    atomicAdd(&g_deg[dst], 1);
}

#define SCAN_BLK 157   // ceil(40000/256)

__global__ void k_scan_part() {
    __shared__ int sh[256];
    int t = threadIdx.x;
    int i = blockIdx.x * 256 + t;
    sh[t] = (i < N_NODES) ? g_deg[i] : 0;
    __syncthreads();
    for (int off = 128; off > 0; off >>= 1) {
        if (t < off) sh[t] += sh[t + off];
        __syncthreads();
    }
    if (t == 0) g_bsum[blockIdx.x] = sh[0];
}

__global__ void k_scan_top() {
    __shared__ int sh[256];
    int t = threadIdx.x;
    int v = (t < SCAN_BLK) ? g_bsum[t] : 0;
    sh[t] = v;
    __syncthreads();
    for (int off = 1; off < 256; off <<= 1) {
        int x = (t >= off) ? sh[t - off] : 0;
        __syncthreads();
        sh[t] += x;
        __syncthreads();
    }
    if (t < SCAN_BLK) g_boff[t] = sh[t] - v;   // exclusive
    if (t == 0) g_rowptr[N_NODES] = N_EDGES;
}

__global__ void k_scan_wr() {
    __shared__ int sh[256];
    int t = threadIdx.x;
    int i = blockIdx.x * 256 + t;
    int v = (i < N_NODES) ? g_deg[i] : 0;
    sh[t] = v;
    __syncthreads();
    for (int off = 1; off < 256; off <<= 1) {
        int x = (t >= off) ? sh[t - off] : 0;
        __syncthreads();
        sh[t] += x;
        __syncthreads();
    }
    if (i < N_NODES) g_rowptr[i] = g_boff[blockIdx.x] + sh[t] - v;
}

__global__ void k_fill(const int* __restrict__ ew) {
    int e = blockIdx.x * blockDim.x + threadIdx.x;
    if (e >= N_EDGES) return;
    int is64 = g_is64;
    int src = is64 ? ew[2 * e] : ew[e];
    int dst = is64 ? ew[2 * (N_EDGES + e)] : ew[N_EDGES + e];
    int pos = atomicAdd(&g_fill[dst], 1);
    g_colidx[g_rowptr[dst] + pos] = src;
}

// ======================= edge aggregation (1 warp / node) ==================
__global__ void __launch_bounds__(256) k_agg(const float* __restrict__ xext, int in_sel) {
    const float* xin = (in_sel == 0) ? xext : (in_sel == 1 ? g_h0 : g_h1);
    int gwarp = (blockIdx.x * blockDim.x + threadIdx.x) >> 5;
    int lane = threadIdx.x & 31;
    if (gwarp >= N_NODES) return;
    int beg = g_rowptr[gwarp];
    int end = g_rowptr[gwarp + 1];
    float4 acc = make_float4(0.f, 0.f, 0.f, 0.f);
    int e = beg;
    for (; e + 3 < end; e += 4) {
        int s0 = g_colidx[e + 0];
        int s1 = g_colidx[e + 1];
        int s2 = g_colidx[e + 2];
        int s3 = g_colidx[e + 3];
        float4 v0 = __ldg((const float4*)(xin + (size_t)s0 * DF) + lane);
        float4 v1 = __ldg((const float4*)(xin + (size_t)s1 * DF) + lane);
        float4 v2 = __ldg((const float4*)(xin + (size_t)s2 * DF) + lane);
        float4 v3 = __ldg((const float4*)(xin + (size_t)s3 * DF) + lane);
        acc.x += (v0.x + v1.x) + (v2.x + v3.x);
        acc.y += (v0.y + v1.y) + (v2.y + v3.y);
        acc.z += (v0.z + v1.z) + (v2.z + v3.z);
        acc.w += (v0.w + v1.w) + (v2.w + v3.w);
    }
    for (; e < end; e++) {
        int s0 = g_colidx[e];
        float4 v0 = __ldg((const float4*)(xin + (size_t)s0 * DF) + lane);
        acc.x += v0.x; acc.y += v0.y; acc.z += v0.z; acc.w += v0.w;
    }
    *((float4*)(g_agg + (size_t)gwarp * DF) + lane) = acc;
}

// ======================= tf32 mma.sync GEMM ================================
// Per CTA: 128 rows out = [g_agg | root] (K=256) @ WT^T (N=128), + bias, ReLU.
// 256 threads = 8 warps in 4(m) x 2(n); warp tile 32x64; mma m16n8k8 tf32.
// Smem stride 36 words: fragment LDS is bank-conflict-free (8 rows x +4 banks
// x 4 cols covers all 32 banks), and 144B rows keep uint4 fills 16B-aligned.
#define GSTR 36

__global__ void __launch_bounds__(256) k_gemm_mma(
    const float* __restrict__ xext, int root_sel, int out_sel, int layer,
    const float* __restrict__ bias, int do_relu)
{
    __shared__ uint32_t sA[128 * GSTR];   // [m][k] tf32 bits
    __shared__ uint32_t sB[128 * GSTR];   // [n][k] tf32 bits

    const float* Aroot = (root_sel == 0) ? xext : (root_sel == 1 ? g_h0 : g_h1);
    float* out = (out_sel == 0) ? g_h0 : g_h1;

    int tid = threadIdx.x;
    int wid = tid >> 5;
    int lane = tid & 31;
    int row0 = blockIdx.x * 128;
    int wm = wid & 3;          // warp m index (0..3) -> rows wm*32..+31
    int wn = wid >> 2;         // warp n index (0..1) -> cols wn*64..+63
    int lq = lane >> 2;        // lane/4 (0..7)
    int lr = lane & 3;         // lane%4 (0..3)

    const float* Bsrc = &g_WT[layer][0][0];

    float acc[2][8][4];
    #pragma unroll
    for (int mt = 0; mt < 2; mt++)
        #pragma unroll
        for (int nt = 0; nt < 8; nt++)
            #pragma unroll
            for (int q = 0; q < 4; q++) acc[mt][nt][q] = 0.f;

    for (int c = 0; c < 8; c++) {
        int kbase = c * 32;
        const float* Asrc = (kbase < 128) ? g_agg : Aroot;
        int acol = kbase & 127;

        // fill A: 128 rows x 8 float4 = 1024 float4 over 256 threads
        #pragma unroll
        for (int it = 0; it < 4; it++) {
            int idx = it * 256 + tid;
            int r = idx >> 3, c4 = idx & 7;
            int grow = row0 + r;
            float4 v = make_float4(0.f, 0.f, 0.f, 0.f);
            if (grow < N_NODES)
                v = *(const float4*)(Asrc + (size_t)grow * DF + acol + c4 * 4);
            uint4 p;
            p.x = f2tf32(v.x); p.y = f2tf32(v.y);
            p.z = f2tf32(v.z); p.w = f2tf32(v.w);
            *(uint4*)&sA[r * GSTR + c4 * 4] = p;
        }
        // fill B from WT[n][kbase..+31]
        #pragma unroll
        for (int it = 0; it < 4; it++) {
            int idx = it * 256 + tid;
            int n = idx >> 3, c4 = idx & 7;
            float4 v = *(const float4*)(Bsrc + (size_t)n * 256 + kbase + c4 * 4);
            uint4 p;
            p.x = f2tf32(v.x); p.y = f2tf32(v.y);
            p.z = f2tf32(v.z); p.w = f2tf32(v.w);
            *(uint4*)&sB[n * GSTR + c4 * 4] = p;
        }
        __syncthreads();

        #pragma unroll
        for (int ks = 0; ks < 4; ks++) {
            int k0 = ks * 8;
            uint32_t a[2][4];
            #pragma unroll
            for (int mt = 0; mt < 2; mt++) {
                int mrow = wm * 32 + mt * 16;
                a[mt][0] = sA[(mrow + lq    ) * GSTR + k0 + lr    ];
                a[mt][1] = sA[(mrow + lq + 8) * GSTR + k0 + lr    ];
                a[mt][2] = sA[(mrow + lq    ) * GSTR + k0 + lr + 4];
                a[mt][3] = sA[(mrow + lq + 8) * GSTR + k0 + lr + 4];
            }
            #pragma unroll
            for (int nt = 0; nt < 8; nt++) {
                int ncol = wn * 64 + nt * 8;
                uint32_t b0 = sB[(ncol + lq) * GSTR + k0 + lr    ];
                uint32_t b1 = sB[(ncol + lq) * GSTR + k0 + lr + 4];
                MMA_TF32(acc[0][nt], a[0], b0, b1);
                MMA_TF32(acc[1][nt], a[1], b0, b1);
            }
        }
        __syncthreads();
    }

    // epilogue: fragment layout c0:(row=lq, col=lr*2) c1:(col+1) c2/c3:(row+8)
    #pragma unroll
    for (int mt = 0; mt < 2; mt++) {
        int r_lo = row0 + wm * 32 + mt * 16 + lq;
        int r_hi = r_lo + 8;
        #pragma unroll
        for (int nt = 0; nt < 8; nt++) {
            int col = wn * 64 + nt * 8 + lr * 2;
            float bx = bias[col], by = bias[col + 1];
            float2 lo, hi;
            lo.x = acc[mt][nt][0] + bx; lo.y = acc[mt][nt][1] + by;
            hi.x = acc[mt][nt][2] + bx; hi.y = acc[mt][nt][3] + by;
            if (do_relu) {
                lo.x = fmaxf(lo.x, 0.f); lo.y = fmaxf(lo.y, 0.f);
                hi.x = fmaxf(hi.x, 0.f); hi.y = fmaxf(hi.y, 0.f);
            }
            if (r_lo < N_NODES) *(float2*)(out + (size_t)r_lo * DF + col) = lo;
            if (r_hi < N_NODES) *(float2*)(out + (size_t)r_hi * DF + col) = hi;
        }
    }
}

// ======================= pool + decode =====================================
__global__ void k_pool(const int* __restrict__ batch) {
    int idx = blockIdx.x * blockDim.x + threadIdx.x;
    if (idx >= N_NODES * 32) return;
    int node = idx >> 5;
    int c = (idx & 31) * 4;
    int g = g_is64 ? batch[2 * node] : batch[node];
    float4 v = *(const float4*)(g_h0 + (size_t)node * DF + c);
    unsigned* o = &g_outmax[g * DF + c];
    atomicMax(o + 0, enc_f(v.x));
    atomicMax(o + 1, enc_f(v.y));
    atomicMax(o + 2, enc_f(v.z));
    atomicMax(o + 3, enc_f(v.w));
}

__global__ void k_decode(float* __restrict__ out) {
    int i = blockIdx.x * blockDim.x + threadIdx.x;
    if (i < N_GRAPHS * DF) out[i] = dec_f(g_outmax[i]);
}

// ===========================================================================
extern "C" void kernel_launch(void* const* d_in, const int* in_sizes, int n_in,
                              void* d_out, int out_size) {
    const float* x      = (const float*)d_in[0];
    const int*   edges  = (const int*)  d_in[1];   // int32 or int64 (probed)
    const int*   batch  = (const int*)  d_in[2];
    const float* Wrel0  = (const float*)d_in[3];
    const float* brel0  = (const float*)d_in[4];
    const float* Wroot0 = (const float*)d_in[5];
    const float* Wrel1  = (const float*)d_in[6];
    const float* brel1  = (const float*)d_in[7];
    const float* Wroot1 = (const float*)d_in[8];
    const float* Wrel2  = (const float*)d_in[9];
    const float* brel2  = (const float*)d_in[10];
    const float* Wroot2 = (const float*)d_in[11];
    float* out = (float*)d_out;

    k_probe<<<1, 1>>>(edges);
    k_zero<<<(N_NODES + 255) / 256, 256>>>();
    k_wprep<<<(DF * 256 + 255) / 256, 256>>>(Wrel0, Wroot0, 0);
    k_wprep<<<(DF * 256 + 255) / 256, 256>>>(Wrel1, Wroot1, 1);
    k_wprep<<<(DF * 256 + 255) / 256, 256>>>(Wrel2, Wroot2, 2);
    k_count<<<N_EDGES / 256, 256>>>(edges);
    k_scan_part<<<SCAN_BLK, 256>>>();
    k_scan_top<<<1, 256>>>();
    k_scan_wr<<<SCAN_BLK, 256>>>();
    k_fill<<<N_EDGES / 256, 256>>>(edges);

    const int AGG_BLOCKS = N_NODES / 8;            // 8 warps/block, 1 node/warp
    const int GEMM_BLOCKS = (N_NODES + 127) / 128; // 313

    // layer 0: agg(x) -> gemm([agg|x]) -> h0 (ReLU)
    k_agg<<<AGG_BLOCKS, 256>>>(x, 0);
    k_gemm_mma<<<GEMM_BLOCKS, 256>>>(x, 0, 0, 0, brel0, 1);
    // layer 1: agg(h0) -> gemm([agg|h0]) -> h1 (ReLU)
    k_agg<<<AGG_BLOCKS, 256>>>(x, 1);
    k_gemm_mma<<<GEMM_BLOCKS, 256>>>(x, 1, 1, 1, brel1, 1);
    // layer 2: agg(h1) -> gemm([agg|h1]) -> h0 (no ReLU)
    k_agg<<<AGG_BLOCKS, 256>>>(x, 2);
    k_gemm_mma<<<GEMM_BLOCKS, 256>>>(x, 2, 0, 2, brel2, 0);

    // pool + decode
    k_pool<<<(N_NODES * 32 + 255) / 256, 256>>>(batch);
    k_decode<<<(N_GRAPHS * DF + 255) / 256, 256>>>(out);
}

// round 9
// speedup vs baseline: 1.9342x; 1.2129x over previous
#include <cuda_runtime.h>
#include <cstdint>

#define N_NODES 40000
#define N_EDGES 640000
#define DF      128
#define N_GRAPHS 128

// ======================= scratch (static device globals) ====================
__device__ float g_agg[(size_t)N_NODES * DF];
__device__ float g_h0 [(size_t)N_NODES * DF];
__device__ float g_h1 [(size_t)N_NODES * DF];
__device__ float g_WT [3][DF][256];          // [layer][n][k_cat] transposed weights
__device__ int   g_rowptr[N_NODES + 1];
__device__ int   g_deg [N_NODES];
__device__ int   g_fill[N_NODES];
__device__ int   g_colidx[N_EDGES];
__device__ int   g_bsum[160];
__device__ int   g_boff[160];
__device__ unsigned g_outmax[N_GRAPHS * DF];
__device__ int   g_is64;

// ======================= helpers ===========================================
__device__ __forceinline__ uint32_t f2tf32(float f) {
    uint32_t r;
    asm("cvt.rna.tf32.f32 %0, %1;" : "=r"(r) : "f"(f));
    return r;
}

// mma.sync m16n8k8 tf32: D(4f) = A(4r) * B(2r) + D
#define MMA_TF32(d, a, b0, b1)                                                \
    asm volatile("mma.sync.aligned.m16n8k8.row.col.f32.tf32.tf32.f32 "        \
        "{%0,%1,%2,%3}, {%4,%5,%6,%7}, {%8,%9}, {%0,%1,%2,%3};"               \
        : "+f"((d)[0]), "+f"((d)[1]), "+f"((d)[2]), "+f"((d)[3])              \
        : "r"((a)[0]), "r"((a)[1]), "r"((a)[2]), "r"((a)[3]),                 \
          "r"(b0), "r"(b1))

__device__ __forceinline__ unsigned enc_f(float f) {
    unsigned b = __float_as_uint(f);
    return (b & 0x80000000u) ? ~b : (b | 0x80000000u);
}
__device__ __forceinline__ float dec_f(unsigned u) {
    unsigned b = (u & 0x80000000u) ? (u ^ 0x80000000u) : ~u;
    return __uint_as_float(b);
}
#define ENC_NEG_INF 0x007FFFFFu

// ======================= zero/init + PARALLEL probe ========================
// Block 0 also probes int64-vs-int32: 256 threads each test one odd word
// (all-zero odd words <=> int64, since node ids < 2^17). One load per thread.
__global__ void k_zero(const int* __restrict__ ew) {
    __shared__ int s_any;
    int i = blockIdx.x * blockDim.x + threadIdx.x;
    if (i < N_NODES) { g_deg[i] = 0; g_fill[i] = 0; }
    if (i < N_GRAPHS * DF) g_outmax[i] = ENC_NEG_INF;
    if (blockIdx.x == 0) {
        if (threadIdx.x == 0) s_any = 0;
        __syncthreads();
        if (ew[2 * threadIdx.x + 1] != 0) atomicOr(&s_any, 1);
        __syncthreads();
        if (threadIdx.x == 0) g_is64 = s_any ? 0 : 1;
    }
}

// ======================= weight transpose: WT[n][k_cat] (all 3 layers) =====
__global__ void k_wprep(const float* __restrict__ Wrel0, const float* __restrict__ Wroot0,
                        const float* __restrict__ Wrel1, const float* __restrict__ Wroot1,
                        const float* __restrict__ Wrel2, const float* __restrict__ Wroot2) {
    int gidx = blockIdx.x * blockDim.x + threadIdx.x;
    int layer = gidx / (DF * 256);
    int idx = gidx % (DF * 256);
    if (layer >= 3) return;
    const float* Wrel  = (layer == 0) ? Wrel0  : (layer == 1) ? Wrel1  : Wrel2;
    const float* Wroot = (layer == 0) ? Wroot0 : (layer == 1) ? Wroot1 : Wroot2;
    int n = idx >> 8;
    int k = idx & 255;
    float v = (k < DF) ? Wrel[k * DF + n] : Wroot[(k - DF) * DF + n];
    g_WT[layer][n][k] = v;
}

// ======================= CSR build =========================================
__global__ void k_count(const int* __restrict__ ew) {
    int e = blockIdx.x * blockDim.x + threadIdx.x;
    if (e >= N_EDGES) return;
    int dst = g_is64 ? ew[2 * (N_EDGES + e)] : ew[N_EDGES + e];
    atomicAdd(&g_deg[dst], 1);
}

#define SCAN_BLK 157   // ceil(40000/256)

__global__ void k_scan_part() {
    __shared__ int sh[256];
    int t = threadIdx.x;
    int i = blockIdx.x * 256 + t;
    sh[t] = (i < N_NODES) ? g_deg[i] : 0;
    __syncthreads();
    for (int off = 128; off > 0; off >>= 1) {
        if (t < off) sh[t] += sh[t + off];
        __syncthreads();
    }
    if (t == 0) g_bsum[blockIdx.x] = sh[0];
}

__global__ void k_scan_top() {
    __shared__ int sh[256];
    int t = threadIdx.x;
    int v = (t < SCAN_BLK) ? g_bsum[t] : 0;
    sh[t] = v;
    __syncthreads();
    for (int off = 1; off < 256; off <<= 1) {
        int x = (t >= off) ? sh[t - off] : 0;
        __syncthreads();
        sh[t] += x;
        __syncthreads();
    }
    if (t < SCAN_BLK) g_boff[t] = sh[t] - v;   // exclusive
    if (t == 0) g_rowptr[N_NODES] = N_EDGES;
}

__global__ void k_scan_wr() {
    __shared__ int sh[256];
    int t = threadIdx.x;
    int i = blockIdx.x * 256 + t;
    int v = (i < N_NODES) ? g_deg[i] : 0;
    sh[t] = v;
    __syncthreads();
    for (int off = 1; off < 256; off <<= 1) {
        int x = (t >= off) ? sh[t - off] : 0;
        __syncthreads();
        sh[t] += x;
        __syncthreads();
    }
    if (i < N_NODES) g_rowptr[i] = g_boff[blockIdx.x] + sh[t] - v;
}

__global__ void k_fill(const int* __restrict__ ew) {
    int e = blockIdx.x * blockDim.x + threadIdx.x;
    if (e >= N_EDGES) return;
    int is64 = g_is64;
    int src = is64 ? ew[2 * e] : ew[e];
    int dst = is64 ? ew[2 * (N_EDGES + e)] : ew[N_EDGES + e];
    int pos = atomicAdd(&g_fill[dst], 1);
    g_colidx[g_rowptr[dst] + pos] = src;
}

// ======================= edge aggregation (1 warp / node) ==================
__global__ void __launch_bounds__(256) k_agg(const float* __restrict__ xext, int in_sel) {
    const float* xin = (in_sel == 0) ? xext : (in_sel == 1 ? g_h0 : g_h1);
    int gwarp = (blockIdx.x * blockDim.x + threadIdx.x) >> 5;
    int lane = threadIdx.x & 31;
    if (gwarp >= N_NODES) return;
    int beg = g_rowptr[gwarp];
    int end = g_rowptr[gwarp + 1];
    float4 acc = make_float4(0.f, 0.f, 0.f, 0.f);
    int e = beg;
    for (; e + 3 < end; e += 4) {
        int s0 = g_colidx[e + 0];
        int s1 = g_colidx[e + 1];
        int s2 = g_colidx[e + 2];
        int s3 = g_colidx[e + 3];
        float4 v0 = __ldg((const float4*)(xin + (size_t)s0 * DF) + lane);
        float4 v1 = __ldg((const float4*)(xin + (size_t)s1 * DF) + lane);
        float4 v2 = __ldg((const float4*)(xin + (size_t)s2 * DF) + lane);
        float4 v3 = __ldg((const float4*)(xin + (size_t)s3 * DF) + lane);
        acc.x += (v0.x + v1.x) + (v2.x + v3.x);
        acc.y += (v0.y + v1.y) + (v2.y + v3.y);
        acc.z += (v0.z + v1.z) + (v2.z + v3.z);
        acc.w += (v0.w + v1.w) + (v2.w + v3.w);
    }
    for (; e < end; e++) {
        int s0 = g_colidx[e];
        float4 v0 = __ldg((const float4*)(xin + (size_t)s0 * DF) + lane);
        acc.x += v0.x; acc.y += v0.y; acc.z += v0.z; acc.w += v0.w;
    }
    *((float4*)(g_agg + (size_t)gwarp * DF) + lane) = acc;
}

// ======================= tf32 mma.sync GEMM ================================
// Per CTA: 128 rows out = [g_agg | root] (K=256) @ WT^T (N=128), + bias, ReLU.
// 256 threads = 8 warps in 4(m) x 2(n); warp tile 32x64; mma m16n8k8 tf32.
// Smem stride 36 words: fragment LDS is bank-conflict-free and uint4-aligned.
#define GSTR 36

__global__ void __launch_bounds__(256) k_gemm_mma(
    const float* __restrict__ xext, int root_sel, int out_sel, int layer,
    const float* __restrict__ bias, int do_relu)
{
    __shared__ uint32_t sA[128 * GSTR];   // [m][k] tf32 bits
    __shared__ uint32_t sB[128 * GSTR];   // [n][k] tf32 bits

    const float* Aroot = (root_sel == 0) ? xext : (root_sel == 1 ? g_h0 : g_h1);
    float* out = (out_sel == 0) ? g_h0 : g_h1;

    int tid = threadIdx.x;
    int wid = tid >> 5;
    int lane = tid & 31;
    int row0 = blockIdx.x * 128;
    int wm = wid & 3;
    int wn = wid >> 2;
    int lq = lane >> 2;
    int lr = lane & 3;

    const float* Bsrc = &g_WT[layer][0][0];

    float acc[2][8][4];
    #pragma unroll
    for (int mt = 0; mt < 2; mt++)
        #pragma unroll
        for (int nt = 0; nt < 8; nt++)
            #pragma unroll
            for (int q = 0; q < 4; q++) acc[mt][nt][q] = 0.f;

    for (int c = 0; c < 8; c++) {
        int kbase = c * 32;
        const float* Asrc = (kbase < 128) ? g_agg : Aroot;
        int acol = kbase & 127;

        #pragma unroll
        for (int it = 0; it < 4; it++) {
            int idx = it * 256 + tid;
            int r = idx >> 3, c4 = idx & 7;
            int grow = row0 + r;
            float4 v = make_float4(0.f, 0.f, 0.f, 0.f);
            if (grow < N_NODES)
                v = *(const float4*)(Asrc + (size_t)grow * DF + acol + c4 * 4);
            uint4 p;
            p.x = f2tf32(v.x); p.y = f2tf32(v.y);
            p.z = f2tf32(v.z); p.w = f2tf32(v.w);
            *(uint4*)&sA[r * GSTR + c4 * 4] = p;
        }
        #pragma unroll
        for (int it = 0; it < 4; it++) {
            int idx = it * 256 + tid;
            int n = idx >> 3, c4 = idx & 7;
            float4 v = *(const float4*)(Bsrc + (size_t)n * 256 + kbase + c4 * 4);
            uint4 p;
            p.x = f2tf32(v.x); p.y = f2tf32(v.y);
            p.z = f2tf32(v.z); p.w = f2tf32(v.w);
            *(uint4*)&sB[n * GSTR + c4 * 4] = p;
        }
        __syncthreads();

        #pragma unroll
        for (int ks = 0; ks < 4; ks++) {
            int k0 = ks * 8;
            uint32_t a[2][4];
            #pragma unroll
            for (int mt = 0; mt < 2; mt++) {
                int mrow = wm * 32 + mt * 16;
                a[mt][0] = sA[(mrow + lq    ) * GSTR + k0 + lr    ];
                a[mt][1] = sA[(mrow + lq + 8) * GSTR + k0 + lr    ];
                a[mt][2] = sA[(mrow + lq    ) * GSTR + k0 + lr + 4];
                a[mt][3] = sA[(mrow + lq + 8) * GSTR + k0 + lr + 4];
            }
            #pragma unroll
            for (int nt = 0; nt < 8; nt++) {
                int ncol = wn * 64 + nt * 8;
                uint32_t b0 = sB[(ncol + lq) * GSTR + k0 + lr    ];
                uint32_t b1 = sB[(ncol + lq) * GSTR + k0 + lr + 4];
                MMA_TF32(acc[0][nt], a[0], b0, b1);
                MMA_TF32(acc[1][nt], a[1], b0, b1);
            }
        }
        __syncthreads();
    }

    #pragma unroll
    for (int mt = 0; mt < 2; mt++) {
        int r_lo = row0 + wm * 32 + mt * 16 + lq;
        int r_hi = r_lo + 8;
        #pragma unroll
        for (int nt = 0; nt < 8; nt++) {
            int col = wn * 64 + nt * 8 + lr * 2;
            float bx = bias[col], by = bias[col + 1];
            float2 lo, hi;
            lo.x = acc[mt][nt][0] + bx; lo.y = acc[mt][nt][1] + by;
            hi.x = acc[mt][nt][2] + bx; hi.y = acc[mt][nt][3] + by;
            if (do_relu) {
                lo.x = fmaxf(lo.x, 0.f); lo.y = fmaxf(lo.y, 0.f);
                hi.x = fmaxf(hi.x, 0.f); hi.y = fmaxf(hi.y, 0.f);
            }
            if (r_lo < N_NODES) *(float2*)(out + (size_t)r_lo * DF + col) = lo;
            if (r_hi < N_NODES) *(float2*)(out + (size_t)r_hi * DF + col) = hi;
        }
    }
}

// ======================= pool (run-combining, batch is sorted) =============
// Thread: 8 consecutive nodes x 4 columns; local max per graph-run, one
// atomic burst per run boundary. ~8x fewer atomics than per-node version.
#define POOL_NPT 8
__global__ void k_pool(const int* __restrict__ batch) {
    int idx = blockIdx.x * blockDim.x + threadIdx.x;
    const int NGRP = N_NODES / POOL_NPT;     // 5000
    if (idx >= NGRP * 32) return;
    int grp = idx >> 5;
    int c = (idx & 31) * 4;
    int n0 = grp * POOL_NPT;
    int is64 = g_is64;

    int curg = -1;
    float4 m = make_float4(0.f, 0.f, 0.f, 0.f);
    #pragma unroll
    for (int i = 0; i < POOL_NPT; i++) {
        int node = n0 + i;
        int g = is64 ? batch[2 * node] : batch[node];
        float4 v = *(const float4*)(g_h0 + (size_t)node * DF + c);
        if (g != curg) {
            if (curg >= 0) {
                unsigned* o = &g_outmax[curg * DF + c];
                atomicMax(o + 0, enc_f(m.x));
                atomicMax(o + 1, enc_f(m.y));
                atomicMax(o + 2, enc_f(m.z));
                atomicMax(o + 3, enc_f(m.w));
            }
            curg = g; m = v;
        } else {
            m.x = fmaxf(m.x, v.x); m.y = fmaxf(m.y, v.y);
            m.z = fmaxf(m.z, v.z); m.w = fmaxf(m.w, v.w);
        }
    }
    unsigned* o = &g_outmax[curg * DF + c];
    atomicMax(o + 0, enc_f(m.x));
    atomicMax(o + 1, enc_f(m.y));
    atomicMax(o + 2, enc_f(m.z));
    atomicMax(o + 3, enc_f(m.w));
}

__global__ void k_decode(float* __restrict__ out) {
    int i = blockIdx.x * blockDim.x + threadIdx.x;
    if (i < N_GRAPHS * DF) out[i] = dec_f(g_outmax[i]);
}

// ===========================================================================
extern "C" void kernel_launch(void* const* d_in, const int* in_sizes, int n_in,
                              void* d_out, int out_size) {
    const float* x      = (const float*)d_in[0];
    const int*   edges  = (const int*)  d_in[1];   // int32 or int64 (probed)
    const int*   batch  = (const int*)  d_in[2];
    const float* Wrel0  = (const float*)d_in[3];
    const float* brel0  = (const float*)d_in[4];
    const float* Wroot0 = (const float*)d_in[5];
    const float* Wrel1  = (const float*)d_in[6];
    const float* brel1  = (const float*)d_in[7];
    const float* Wroot1 = (const float*)d_in[8];
    const float* Wrel2  = (const float*)d_in[9];
    const float* brel2  = (const float*)d_in[10];
    const float* Wroot2 = (const float*)d_in[11];
    float* out = (float*)d_out;

    k_zero<<<(N_NODES + 255) / 256, 256>>>(edges);   // includes parallel probe
    k_wprep<<<(3 * DF * 256 + 255) / 256, 256>>>(Wrel0, Wroot0, Wrel1, Wroot1, Wrel2, Wroot2);
    k_count<<<N_EDGES / 256, 256>>>(edges);
    k_scan_part<<<SCAN_BLK, 256>>>();
    k_scan_top<<<1, 256>>>();
    k_scan_wr<<<SCAN_BLK, 256>>>();
    k_fill<<<N_EDGES / 256, 256>>>(edges);

    const int AGG_BLOCKS = N_NODES / 8;            // 8 warps/block, 1 node/warp
    const int GEMM_BLOCKS = (N_NODES + 127) / 128; // 313

    // layer 0: agg(x) -> gemm([agg|x]) -> h0 (ReLU)
    k_agg<<<AGG_BLOCKS, 256>>>(x, 0);
    k_gemm_mma<<<GEMM_BLOCKS, 256>>>(x, 0, 0, 0, brel0, 1);
    // layer 1: agg(h0) -> gemm([agg|h0]) -> h1 (ReLU)
    k_agg<<<AGG_BLOCKS, 256>>>(x, 1);
    k_gemm_mma<<<GEMM_BLOCKS, 256>>>(x, 1, 1, 1, brel1, 1);
    // layer 2: agg(h1) -> gemm([agg|h1]) -> h0 (no ReLU)
    k_agg<<<AGG_BLOCKS, 256>>>(x, 2);
    k_gemm_mma<<<GEMM_BLOCKS, 256>>>(x, 2, 0, 2, brel2, 0);

    // pool + decode
    k_pool<<<(N_NODES / POOL_NPT * 32 + 255) / 256, 256>>>(batch);
    k_decode<<<(N_GRAPHS * DF + 255) / 256, 256>>>(out);
}